// round 1
// baseline (speedup 1.0000x reference)
#include <cuda_runtime.h>
#include <math_constants.h>

#define S_  4096
#define D_  512
#define H_  8
#define PD_ 64

// Scratch (allocation-free rule: __device__ globals)
__device__ float g_q[H_ * S_ * PD_];
__device__ float g_k[H_ * S_ * PD_];
__device__ float g_v[H_ * S_ * PD_];
__device__ float g_attn[S_ * D_];
__device__ float g_m[H_ * S_];
__device__ float g_linv[H_ * S_];

// ---------------------------------------------------------------------------
// Tiled SGEMM: out[M,N] = X[M,512] @ W[512,N] + bias, M=4096, N=512
// BM=BN=64, BK=16, 256 threads, 4x4 micro-tile.
// split_heads: out laid out [H][S][PD] (n0 is a multiple of 64 == PD).
// ---------------------------------------------------------------------------
__global__ __launch_bounds__(256) void gemm_kernel(
    const float* __restrict__ X, const float* __restrict__ W,
    const float* __restrict__ bias, float* __restrict__ out, int split_heads)
{
    __shared__ float Xs[16][68];   // [k][m], padded
    __shared__ float Ws[16][64];   // [k][n]
    const int tid = threadIdx.x;
    const int tx = tid & 15, ty = tid >> 4;
    const int m0 = blockIdx.y << 6;
    const int n0 = blockIdx.x << 6;

    float acc[4][4] = {};

    for (int k0 = 0; k0 < D_; k0 += 16) {
        {
            int r = tid >> 2;              // 0..63 (m)
            int c = (tid & 3) << 2;        // 0,4,8,12 (k)
            float4 v = *reinterpret_cast<const float4*>(X + (size_t)(m0 + r) * D_ + k0 + c);
            Xs[c + 0][r] = v.x; Xs[c + 1][r] = v.y;
            Xs[c + 2][r] = v.z; Xs[c + 3][r] = v.w;

            int r2 = tid >> 4;             // 0..15 (k)
            int c2 = (tid & 15) << 2;      // n
            *reinterpret_cast<float4*>(&Ws[r2][c2]) =
                *reinterpret_cast<const float4*>(W + (size_t)(k0 + r2) * D_ + n0 + c2);
        }
        __syncthreads();
#pragma unroll
        for (int kk = 0; kk < 16; kk++) {
            float4 a = *reinterpret_cast<const float4*>(&Xs[kk][ty << 2]);
            float4 b = *reinterpret_cast<const float4*>(&Ws[kk][tx << 2]);
            float av[4] = {a.x, a.y, a.z, a.w};
            float bv[4] = {b.x, b.y, b.z, b.w};
#pragma unroll
            for (int i = 0; i < 4; i++)
#pragma unroll
                for (int j = 0; j < 4; j++)
                    acc[i][j] = fmaf(av[i], bv[j], acc[i][j]);
        }
        __syncthreads();
    }

    float4 bb = *reinterpret_cast<const float4*>(bias + n0 + (tx << 2));
    float bvv[4] = {bb.x, bb.y, bb.z, bb.w};

    if (split_heads) {
        int h = n0 >> 6;
        float* base = out + (size_t)h * S_ * PD_;
#pragma unroll
        for (int i = 0; i < 4; i++) {
            int m = m0 + (ty << 2) + i;
            float4 o = make_float4(acc[i][0] + bvv[0], acc[i][1] + bvv[1],
                                   acc[i][2] + bvv[2], acc[i][3] + bvv[3]);
            *reinterpret_cast<float4*>(base + (size_t)m * PD_ + (tx << 2)) = o;
        }
    } else {
#pragma unroll
        for (int i = 0; i < 4; i++) {
            int m = m0 + (ty << 2) + i;
            float4 o = make_float4(acc[i][0] + bvv[0], acc[i][1] + bvv[1],
                                   acc[i][2] + bvv[2], acc[i][3] + bvv[3]);
            *reinterpret_cast<float4*>(out + (size_t)m * D_ + n0 + (tx << 2)) = o;
        }
    }
}

// ---------------------------------------------------------------------------
// Fused attention per (head, 64-query tile).
// Streams 64-key tiles: computes raw scores (written once to wraw = weights
// output region), online softmax (m, l), and PV accumulation in registers.
// Writes merged attn to g_attn and per-row (max, 1/sum) for the normalize pass.
// ---------------------------------------------------------------------------
__global__ __launch_bounds__(256) void attn_kernel(float* __restrict__ wraw)
{
    extern __shared__ float sm[];
    float* Qst = sm;               // [pd][q]  stride 68
    float* Kst = sm + 64 * 68;     // [pd][k]  stride 68
    float* Vs  = sm + 2 * 64 * 68; // [k][d]   stride 68
    float* Pst = sm + 3 * 64 * 68; // [k][q]   stride 68

    const int h  = blockIdx.y;
    const int q0 = blockIdx.x << 6;
    const int tid = threadIdx.x;
    const int tx = tid & 15, ty = tid >> 4;

    // Load Q tile transposed -> Qst[pd][q]
    {
        const float* qptr = g_q + ((size_t)h * S_ + q0) * PD_;
#pragma unroll
        for (int r = 0; r < 4; r++) {
            int row = (tid >> 4) + (r << 4);    // q local
            int c = (tid & 15) << 2;            // pd
            float4 v = *reinterpret_cast<const float4*>(qptr + row * PD_ + c);
            Qst[(c + 0) * 68 + row] = v.x;
            Qst[(c + 1) * 68 + row] = v.y;
            Qst[(c + 2) * 68 + row] = v.z;
            Qst[(c + 3) * 68 + row] = v.w;
        }
    }

    float m_[4], l_[4], acc[4][4];
#pragma unroll
    for (int i = 0; i < 4; i++) {
        m_[i] = -CUDART_INF_F;
        l_[i] = 0.f;
#pragma unroll
        for (int j = 0; j < 4; j++) acc[i][j] = 0.f;
    }

    const float* kbase = g_k + (size_t)h * S_ * PD_;
    const float* vbase = g_v + (size_t)h * S_ * PD_;

    for (int kt = 0; kt < S_ / 64; kt++) {
        // Load K tile transposed -> Kst[pd][k];  V tile direct -> Vs[k][d]
        {
            const float* kptr = kbase + ((size_t)kt << 6) * PD_;
            const float* vptr = vbase + ((size_t)kt << 6) * PD_;
#pragma unroll
            for (int r = 0; r < 4; r++) {
                int row = (tid >> 4) + (r << 4);
                int c = (tid & 15) << 2;
                float4 kv = *reinterpret_cast<const float4*>(kptr + row * PD_ + c);
                Kst[(c + 0) * 68 + row] = kv.x;
                Kst[(c + 1) * 68 + row] = kv.y;
                Kst[(c + 2) * 68 + row] = kv.z;
                Kst[(c + 3) * 68 + row] = kv.w;
                float4 vv = *reinterpret_cast<const float4*>(vptr + row * PD_ + c);
                *reinterpret_cast<float4*>(&Vs[row * 68 + c]) = vv;
            }
        }
        __syncthreads();

        // S tile: s[i][j] = Q[q, :] . K[k, :],  q=q0+ty*4+i, k=kt*64+tx*4+j
        float s[4][4] = {};
#pragma unroll 8
        for (int pd = 0; pd < 64; pd++) {
            float4 a = *reinterpret_cast<const float4*>(&Qst[pd * 68 + (ty << 2)]);
            float4 b = *reinterpret_cast<const float4*>(&Kst[pd * 68 + (tx << 2)]);
            float av[4] = {a.x, a.y, a.z, a.w};
            float bv[4] = {b.x, b.y, b.z, b.w};
#pragma unroll
            for (int i = 0; i < 4; i++)
#pragma unroll
                for (int j = 0; j < 4; j++)
                    s[i][j] = fmaf(av[i], bv[j], s[i][j]);
        }

        // Scale, write raw scores to output weights region
        float* wrow = wraw + ((size_t)h * S_ + q0 + (ty << 2)) * S_ + (kt << 6) + (tx << 2);
#pragma unroll
        for (int i = 0; i < 4; i++) {
            s[i][0] *= 0.125f; s[i][1] *= 0.125f; s[i][2] *= 0.125f; s[i][3] *= 0.125f;
            *reinterpret_cast<float4*>(wrow + (size_t)i * S_) =
                make_float4(s[i][0], s[i][1], s[i][2], s[i][3]);
        }

        // Online softmax update + stash P (exp values) into Pst[k][q]
#pragma unroll
        for (int i = 0; i < 4; i++) {
            float tmax = fmaxf(fmaxf(s[i][0], s[i][1]), fmaxf(s[i][2], s[i][3]));
#pragma unroll
            for (int w = 1; w < 16; w <<= 1)
                tmax = fmaxf(tmax, __shfl_xor_sync(0xffffffffu, tmax, w));
            float mnew = fmaxf(m_[i], tmax);
            float corr = __expf(m_[i] - mnew);
            float p0 = __expf(s[i][0] - mnew);
            float p1 = __expf(s[i][1] - mnew);
            float p2 = __expf(s[i][2] - mnew);
            float p3 = __expf(s[i][3] - mnew);
            float rs = p0 + p1 + p2 + p3;
#pragma unroll
            for (int w = 1; w < 16; w <<= 1)
                rs += __shfl_xor_sync(0xffffffffu, rs, w);
            l_[i] = l_[i] * corr + rs;
            m_[i] = mnew;
            acc[i][0] *= corr; acc[i][1] *= corr; acc[i][2] *= corr; acc[i][3] *= corr;
            int qq = (ty << 2) + i;
            Pst[((tx << 2) + 0) * 68 + qq] = p0;
            Pst[((tx << 2) + 1) * 68 + qq] = p1;
            Pst[((tx << 2) + 2) * 68 + qq] = p2;
            Pst[((tx << 2) + 3) * 68 + qq] = p3;
        }
        __syncthreads();

        // acc += P @ V    (acc[i][j]: q=ty*4+i, d=tx*4+j)
#pragma unroll 8
        for (int k = 0; k < 64; k++) {
            float4 a = *reinterpret_cast<const float4*>(&Pst[k * 68 + (ty << 2)]);
            float4 b = *reinterpret_cast<const float4*>(&Vs[k * 68 + (tx << 2)]);
            float av[4] = {a.x, a.y, a.z, a.w};
            float bv[4] = {b.x, b.y, b.z, b.w};
#pragma unroll
            for (int i = 0; i < 4; i++)
#pragma unroll
                for (int j = 0; j < 4; j++)
                    acc[i][j] = fmaf(av[i], bv[j], acc[i][j]);
        }
        __syncthreads();
    }

    // Epilogue: attn = acc / l ; save row stats for normalize pass
#pragma unroll
    for (int i = 0; i < 4; i++) {
        int q = q0 + (ty << 2) + i;
        float inv = 1.0f / l_[i];
        float4 o = make_float4(acc[i][0] * inv, acc[i][1] * inv,
                               acc[i][2] * inv, acc[i][3] * inv);
        *reinterpret_cast<float4*>(g_attn + (size_t)q * D_ + (h << 6) + (tx << 2)) = o;
        if (tx == 0) {
            g_m[h * S_ + q] = m_[i];
            g_linv[h * S_ + q] = inv;
        }
    }
}

// ---------------------------------------------------------------------------
// In-place normalize of stored raw scores: w = exp(s - m) * inv_l
// ---------------------------------------------------------------------------
__global__ __launch_bounds__(256) void norm_weights(float* __restrict__ w)
{
    size_t idx = (((size_t)blockIdx.x * 256) + threadIdx.x) << 2;
    size_t row = idx >> 12;           // (h*S + q)
    float m = g_m[row];
    float inv = g_linv[row];
    float4 v = *reinterpret_cast<float4*>(w + idx);
    v.x = __expf(v.x - m) * inv;
    v.y = __expf(v.y - m) * inv;
    v.z = __expf(v.z - m) * inv;
    v.w = __expf(v.w - m) * inv;
    *reinterpret_cast<float4*>(w + idx) = v;
}

// ---------------------------------------------------------------------------
extern "C" void kernel_launch(void* const* d_in, const int* in_sizes, int n_in,
                              void* d_out, int out_size)
{
    const float* x1 = (const float*)d_in[0];
    const float* x2 = (const float*)d_in[1];
    const float* x3 = (const float*)d_in[2];
    const float* Wq = (const float*)d_in[3];
    const float* bq = (const float*)d_in[4];
    const float* Wk = (const float*)d_in[5];
    const float* bk = (const float*)d_in[6];
    const float* Wv = (const float*)d_in[7];
    const float* bv = (const float*)d_in[8];
    const float* Wo = (const float*)d_in[9];
    const float* bo = (const float*)d_in[10];

    float* out = (float*)d_out;                  // [S, D] output
    float* wts = out + (size_t)S_ * D_;          // [H, S, S] weights

    float *qb, *kb, *vb, *ab;
    cudaGetSymbolAddress((void**)&qb, g_q);
    cudaGetSymbolAddress((void**)&kb, g_k);
    cudaGetSymbolAddress((void**)&vb, g_v);
    cudaGetSymbolAddress((void**)&ab, g_attn);

    dim3 ggrid(D_ / 64, S_ / 64);
    gemm_kernel<<<ggrid, 256>>>(x1, Wq, bq, qb, 1);
    gemm_kernel<<<ggrid, 256>>>(x2, Wk, bk, kb, 1);
    gemm_kernel<<<ggrid, 256>>>(x3, Wv, bv, vb, 1);

    int smem = 4 * 64 * 68 * (int)sizeof(float);  // 69632 B
    cudaFuncSetAttribute(attn_kernel, cudaFuncAttributeMaxDynamicSharedMemorySize, smem);
    attn_kernel<<<dim3(S_ / 64, H_), 256, smem>>>(wts);

    norm_weights<<<(H_ * (size_t)S_ * S_) / (4 * 256), 256>>>(wts);

    gemm_kernel<<<ggrid, 256>>>(ab, Wo, bo, out, 0);
}

// round 2
// speedup vs baseline: 1.0012x; 1.0012x over previous
#include <cuda_runtime.h>
#include <math_constants.h>

#define S_  4096
#define D_  512
#define H_  8
#define PD_ 64

// Scratch (allocation-free rule: __device__ globals)
__device__ float g_q[H_ * S_ * PD_];
__device__ float g_k[H_ * S_ * PD_];
__device__ float g_v[H_ * S_ * PD_];
__device__ float g_attn[S_ * D_];
__device__ float g_m[H_ * S_];
__device__ float g_linv[H_ * S_];

// ---------------------------------------------------------------------------
// Tiled SGEMM: out[M,N] = X[M,512] @ W[512,N] + bias, M=4096, N=512
// BM=BN=64, BK=16, 256 threads, 4x4 micro-tile.
// split_heads: out laid out [H][S][PD] (n0 is a multiple of 64 == PD).
// ---------------------------------------------------------------------------
__global__ __launch_bounds__(256) void gemm_kernel(
    const float* __restrict__ X, const float* __restrict__ W,
    const float* __restrict__ bias, float* __restrict__ out, int split_heads)
{
    __shared__ float Xs[16][68];   // [k][m], padded
    __shared__ float Ws[16][64];   // [k][n]
    const int tid = threadIdx.x;
    const int tx = tid & 15, ty = tid >> 4;
    const int m0 = blockIdx.y << 6;
    const int n0 = blockIdx.x << 6;

    float acc[4][4] = {};

    for (int k0 = 0; k0 < D_; k0 += 16) {
        {
            int r = tid >> 2;              // 0..63 (m)
            int c = (tid & 3) << 2;        // 0,4,8,12 (k)
            float4 v = *reinterpret_cast<const float4*>(X + (size_t)(m0 + r) * D_ + k0 + c);
            Xs[c + 0][r] = v.x; Xs[c + 1][r] = v.y;
            Xs[c + 2][r] = v.z; Xs[c + 3][r] = v.w;

            int r2 = tid >> 4;             // 0..15 (k)
            int c2 = (tid & 15) << 2;      // n
            *reinterpret_cast<float4*>(&Ws[r2][c2]) =
                *reinterpret_cast<const float4*>(W + (size_t)(k0 + r2) * D_ + n0 + c2);
        }
        __syncthreads();
#pragma unroll
        for (int kk = 0; kk < 16; kk++) {
            float4 a = *reinterpret_cast<const float4*>(&Xs[kk][ty << 2]);
            float4 b = *reinterpret_cast<const float4*>(&Ws[kk][tx << 2]);
            float av[4] = {a.x, a.y, a.z, a.w};
            float bv[4] = {b.x, b.y, b.z, b.w};
#pragma unroll
            for (int i = 0; i < 4; i++)
#pragma unroll
                for (int j = 0; j < 4; j++)
                    acc[i][j] = fmaf(av[i], bv[j], acc[i][j]);
        }
        __syncthreads();
    }

    float4 bb = *reinterpret_cast<const float4*>(bias + n0 + (tx << 2));
    float bvv[4] = {bb.x, bb.y, bb.z, bb.w};

    if (split_heads) {
        int h = n0 >> 6;
        float* base = out + (size_t)h * S_ * PD_;
#pragma unroll
        for (int i = 0; i < 4; i++) {
            int m = m0 + (ty << 2) + i;
            float4 o = make_float4(acc[i][0] + bvv[0], acc[i][1] + bvv[1],
                                   acc[i][2] + bvv[2], acc[i][3] + bvv[3]);
            *reinterpret_cast<float4*>(base + (size_t)m * PD_ + (tx << 2)) = o;
        }
    } else {
#pragma unroll
        for (int i = 0; i < 4; i++) {
            int m = m0 + (ty << 2) + i;
            float4 o = make_float4(acc[i][0] + bvv[0], acc[i][1] + bvv[1],
                                   acc[i][2] + bvv[2], acc[i][3] + bvv[3]);
            *reinterpret_cast<float4*>(out + (size_t)m * D_ + n0 + (tx << 2)) = o;
        }
    }
}

// ---------------------------------------------------------------------------
// Fused attention per (head, 64-query tile).
// Streams 64-key tiles: computes raw scores (written once to wraw = weights
// output region), online softmax (m, l), and PV accumulation in registers.
// Writes merged attn to g_attn and per-row (max, 1/sum) for the normalize pass.
// ---------------------------------------------------------------------------
__global__ __launch_bounds__(256) void attn_kernel(float* __restrict__ wraw)
{
    extern __shared__ float sm[];
    float* Qst = sm;               // [pd][q]  stride 68
    float* Kst = sm + 64 * 68;     // [pd][k]  stride 68
    float* Vs  = sm + 2 * 64 * 68; // [k][d]   stride 68
    float* Pst = sm + 3 * 64 * 68; // [k][q]   stride 68

    const int h  = blockIdx.y;
    const int q0 = blockIdx.x << 6;
    const int tid = threadIdx.x;
    const int tx = tid & 15, ty = tid >> 4;

    // Load Q tile transposed -> Qst[pd][q]
    {
        const float* qptr = g_q + ((size_t)h * S_ + q0) * PD_;
#pragma unroll
        for (int r = 0; r < 4; r++) {
            int row = (tid >> 4) + (r << 4);    // q local
            int c = (tid & 15) << 2;            // pd
            float4 v = *reinterpret_cast<const float4*>(qptr + row * PD_ + c);
            Qst[(c + 0) * 68 + row] = v.x;
            Qst[(c + 1) * 68 + row] = v.y;
            Qst[(c + 2) * 68 + row] = v.z;
            Qst[(c + 3) * 68 + row] = v.w;
        }
    }

    float m_[4], l_[4], acc[4][4];
#pragma unroll
    for (int i = 0; i < 4; i++) {
        m_[i] = -CUDART_INF_F;
        l_[i] = 0.f;
#pragma unroll
        for (int j = 0; j < 4; j++) acc[i][j] = 0.f;
    }

    const float* kbase = g_k + (size_t)h * S_ * PD_;
    const float* vbase = g_v + (size_t)h * S_ * PD_;

    for (int kt = 0; kt < S_ / 64; kt++) {
        // Load K tile transposed -> Kst[pd][k];  V tile direct -> Vs[k][d]
        {
            const float* kptr = kbase + ((size_t)kt << 6) * PD_;
            const float* vptr = vbase + ((size_t)kt << 6) * PD_;
#pragma unroll
            for (int r = 0; r < 4; r++) {
                int row = (tid >> 4) + (r << 4);
                int c = (tid & 15) << 2;
                float4 kv = *reinterpret_cast<const float4*>(kptr + row * PD_ + c);
                Kst[(c + 0) * 68 + row] = kv.x;
                Kst[(c + 1) * 68 + row] = kv.y;
                Kst[(c + 2) * 68 + row] = kv.z;
                Kst[(c + 3) * 68 + row] = kv.w;
                float4 vv = *reinterpret_cast<const float4*>(vptr + row * PD_ + c);
                *reinterpret_cast<float4*>(&Vs[row * 68 + c]) = vv;
            }
        }
        __syncthreads();

        // S tile: s[i][j] = Q[q, :] . K[k, :],  q=q0+ty*4+i, k=kt*64+tx*4+j
        float s[4][4] = {};
#pragma unroll 8
        for (int pd = 0; pd < 64; pd++) {
            float4 a = *reinterpret_cast<const float4*>(&Qst[pd * 68 + (ty << 2)]);
            float4 b = *reinterpret_cast<const float4*>(&Kst[pd * 68 + (tx << 2)]);
            float av[4] = {a.x, a.y, a.z, a.w};
            float bv[4] = {b.x, b.y, b.z, b.w};
#pragma unroll
            for (int i = 0; i < 4; i++)
#pragma unroll
                for (int j = 0; j < 4; j++)
                    s[i][j] = fmaf(av[i], bv[j], s[i][j]);
        }

        // Scale, write raw scores to output weights region
        float* wrow = wraw + ((size_t)h * S_ + q0 + (ty << 2)) * S_ + (kt << 6) + (tx << 2);
#pragma unroll
        for (int i = 0; i < 4; i++) {
            s[i][0] *= 0.125f; s[i][1] *= 0.125f; s[i][2] *= 0.125f; s[i][3] *= 0.125f;
            *reinterpret_cast<float4*>(wrow + (size_t)i * S_) =
                make_float4(s[i][0], s[i][1], s[i][2], s[i][3]);
        }

        // Online softmax update + stash P (exp values) into Pst[k][q]
#pragma unroll
        for (int i = 0; i < 4; i++) {
            float tmax = fmaxf(fmaxf(s[i][0], s[i][1]), fmaxf(s[i][2], s[i][3]));
#pragma unroll
            for (int w = 1; w < 16; w <<= 1)
                tmax = fmaxf(tmax, __shfl_xor_sync(0xffffffffu, tmax, w));
            float mnew = fmaxf(m_[i], tmax);
            float corr = __expf(m_[i] - mnew);
            float p0 = __expf(s[i][0] - mnew);
            float p1 = __expf(s[i][1] - mnew);
            float p2 = __expf(s[i][2] - mnew);
            float p3 = __expf(s[i][3] - mnew);
            float rs = p0 + p1 + p2 + p3;
#pragma unroll
            for (int w = 1; w < 16; w <<= 1)
                rs += __shfl_xor_sync(0xffffffffu, rs, w);
            l_[i] = l_[i] * corr + rs;
            m_[i] = mnew;
            acc[i][0] *= corr; acc[i][1] *= corr; acc[i][2] *= corr; acc[i][3] *= corr;
            int qq = (ty << 2) + i;
            Pst[((tx << 2) + 0) * 68 + qq] = p0;
            Pst[((tx << 2) + 1) * 68 + qq] = p1;
            Pst[((tx << 2) + 2) * 68 + qq] = p2;
            Pst[((tx << 2) + 3) * 68 + qq] = p3;
        }
        __syncthreads();

        // acc += P @ V    (acc[i][j]: q=ty*4+i, d=tx*4+j)
#pragma unroll 8
        for (int k = 0; k < 64; k++) {
            float4 a = *reinterpret_cast<const float4*>(&Pst[k * 68 + (ty << 2)]);
            float4 b = *reinterpret_cast<const float4*>(&Vs[k * 68 + (tx << 2)]);
            float av[4] = {a.x, a.y, a.z, a.w};
            float bv[4] = {b.x, b.y, b.z, b.w};
#pragma unroll
            for (int i = 0; i < 4; i++)
#pragma unroll
                for (int j = 0; j < 4; j++)
                    acc[i][j] = fmaf(av[i], bv[j], acc[i][j]);
        }
        __syncthreads();
    }

    // Epilogue: attn = acc / l ; save row stats for normalize pass
#pragma unroll
    for (int i = 0; i < 4; i++) {
        int q = q0 + (ty << 2) + i;
        float inv = 1.0f / l_[i];
        float4 o = make_float4(acc[i][0] * inv, acc[i][1] * inv,
                               acc[i][2] * inv, acc[i][3] * inv);
        *reinterpret_cast<float4*>(g_attn + (size_t)q * D_ + (h << 6) + (tx << 2)) = o;
        if (tx == 0) {
            g_m[h * S_ + q] = m_[i];
            g_linv[h * S_ + q] = inv;
        }
    }
}

// ---------------------------------------------------------------------------
// In-place normalize of stored raw scores: w = exp(s - m) * inv_l
// ---------------------------------------------------------------------------
__global__ __launch_bounds__(256) void norm_weights(float* __restrict__ w)
{
    size_t idx = (((size_t)blockIdx.x * 256) + threadIdx.x) << 2;
    size_t row = idx >> 12;           // (h*S + q)
    float m = g_m[row];
    float inv = g_linv[row];
    float4 v = *reinterpret_cast<float4*>(w + idx);
    v.x = __expf(v.x - m) * inv;
    v.y = __expf(v.y - m) * inv;
    v.z = __expf(v.z - m) * inv;
    v.w = __expf(v.w - m) * inv;
    *reinterpret_cast<float4*>(w + idx) = v;
}

// ---------------------------------------------------------------------------
extern "C" void kernel_launch(void* const* d_in, const int* in_sizes, int n_in,
                              void* d_out, int out_size)
{
    const float* x1 = (const float*)d_in[0];
    const float* x2 = (const float*)d_in[1];
    const float* x3 = (const float*)d_in[2];
    const float* Wq = (const float*)d_in[3];
    const float* bq = (const float*)d_in[4];
    const float* Wk = (const float*)d_in[5];
    const float* bk = (const float*)d_in[6];
    const float* Wv = (const float*)d_in[7];
    const float* bv = (const float*)d_in[8];
    const float* Wo = (const float*)d_in[9];
    const float* bo = (const float*)d_in[10];

    float* out = (float*)d_out;                  // [S, D] output
    float* wts = out + (size_t)S_ * D_;          // [H, S, S] weights

    float *qb, *kb, *vb, *ab;
    cudaGetSymbolAddress((void**)&qb, g_q);
    cudaGetSymbolAddress((void**)&kb, g_k);
    cudaGetSymbolAddress((void**)&vb, g_v);
    cudaGetSymbolAddress((void**)&ab, g_attn);

    dim3 ggrid(D_ / 64, S_ / 64);
    gemm_kernel<<<ggrid, 256>>>(x1, Wq, bq, qb, 1);
    gemm_kernel<<<ggrid, 256>>>(x2, Wk, bk, kb, 1);
    gemm_kernel<<<ggrid, 256>>>(x3, Wv, bv, vb, 1);

    int smem = 4 * 64 * 68 * (int)sizeof(float);  // 69632 B
    cudaFuncSetAttribute(attn_kernel, cudaFuncAttributeMaxDynamicSharedMemorySize, smem);
    attn_kernel<<<dim3(S_ / 64, H_), 256, smem>>>(wts);

    norm_weights<<<(H_ * (size_t)S_ * S_) / (4 * 256), 256>>>(wts);

    gemm_kernel<<<ggrid, 256>>>(ab, Wo, bo, out, 0);
}

// round 4
// speedup vs baseline: 1.9917x; 1.9893x over previous
#include <cuda_runtime.h>
#include <cuda_bf16.h>
#include <cstdint>
#include <math_constants.h>

#define S_  4096
#define D_  512
#define H_  8
#define PD_ 64
typedef __nv_bfloat16 bf16;

// ------------------------- device scratch -------------------------
__device__ bf16  g_xh[3][S_ * D_], g_xl[3][S_ * D_];
__device__ bf16  g_wth[4][D_ * D_], g_wtl[4][D_ * D_];     // W^T [n][k]
__device__ float g_q[H_ * S_ * PD_], g_k[H_ * S_ * PD_], g_v[H_ * S_ * PD_];
__device__ bf16  g_qh[H_ * S_ * PD_], g_ql[H_ * S_ * PD_];
__device__ bf16  g_kh[H_ * S_ * PD_], g_kl[H_ * S_ * PD_];
__device__ bf16  g_vth[H_ * PD_ * S_], g_vtl[H_ * PD_ * S_]; // V^T per head [pd][s]
__device__ float g_attn[S_ * D_];
__device__ bf16  g_ah[S_ * D_], g_al[S_ * D_];
__device__ float g_m[H_ * S_], g_linv[H_ * S_];

// ------------------------- helpers -------------------------
__device__ __forceinline__ uint32_t smem_u32(const void* p) {
    uint32_t a;
    asm("{ .reg .u64 t; cvta.to.shared.u64 t, %1; cvt.u32.u64 %0, t; }" : "=r"(a) : "l"(p));
    return a;
}
__device__ __forceinline__ void ldsm4(uint32_t addr, uint32_t& r0, uint32_t& r1,
                                      uint32_t& r2, uint32_t& r3) {
    asm volatile("ldmatrix.sync.aligned.m8n8.x4.shared.b16 {%0,%1,%2,%3}, [%4];"
                 : "=r"(r0), "=r"(r1), "=r"(r2), "=r"(r3) : "r"(addr));
}
__device__ __forceinline__ void mma_bf(float c[4], const uint32_t a[4],
                                       uint32_t b0, uint32_t b1) {
    asm volatile("mma.sync.aligned.m16n8k16.row.col.f32.bf16.bf16.f32 "
                 "{%0,%1,%2,%3}, {%4,%5,%6,%7}, {%8,%9}, {%0,%1,%2,%3};"
                 : "+f"(c[0]), "+f"(c[1]), "+f"(c[2]), "+f"(c[3])
                 : "r"(a[0]), "r"(a[1]), "r"(a[2]), "r"(a[3]), "r"(b0), "r"(b1));
}
__device__ __forceinline__ void split2(float v, bf16& h, bf16& l) {
    h = __float2bfloat16(v);
    l = __float2bfloat16(v - __bfloat162float(h));
}
__device__ __forceinline__ void bsplitpack(float x, float y, uint32_t& hi, uint32_t& lo) {
    bf16 xh, xl, yh, yl;
    split2(x, xh, xl); split2(y, yh, yl);
    __nv_bfloat162 h2, l2;
    h2.x = xh; h2.y = yh; l2.x = xl; l2.y = yl;
    hi = *reinterpret_cast<uint32_t*>(&h2);
    lo = *reinterpret_cast<uint32_t*>(&l2);
}

// ------------------------- split / transpose kernels -------------------------
__global__ __launch_bounds__(256) void split_kernel(const float* __restrict__ in,
                                                    bf16* __restrict__ oh, bf16* __restrict__ ol) {
    size_t i = ((size_t)blockIdx.x * 256 + threadIdx.x) * 4;
    float4 v = *reinterpret_cast<const float4*>(in + i);
    bf16 h0,h1,h2,h3,l0,l1,l2,l3;
    split2(v.x,h0,l0); split2(v.y,h1,l1); split2(v.z,h2,l2); split2(v.w,h3,l3);
    __nv_bfloat162 ha{h0,h1}, hb{h2,h3}, la{l0,l1}, lb{l2,l3};
    reinterpret_cast<__nv_bfloat162*>(oh + i)[0] = ha;
    reinterpret_cast<__nv_bfloat162*>(oh + i)[1] = hb;
    reinterpret_cast<__nv_bfloat162*>(ol + i)[0] = la;
    reinterpret_cast<__nv_bfloat162*>(ol + i)[1] = lb;
}

__global__ __launch_bounds__(256) void transpose_split(const float* __restrict__ in,
                                                       bf16* __restrict__ oh, bf16* __restrict__ ol,
                                                       int R, int C) {
    __shared__ float t[32][33];
    size_t base = (size_t)blockIdx.z * R * C;
    int r0 = blockIdx.y * 32, c0 = blockIdx.x * 32;
    for (int i = threadIdx.y; i < 32; i += 8)
        t[i][threadIdx.x] = in[base + (size_t)(r0 + i) * C + c0 + threadIdx.x];
    __syncthreads();
    for (int i = threadIdx.y; i < 32; i += 8) {
        bf16 h, l; split2(t[threadIdx.x][i], h, l);
        size_t o = base + (size_t)(c0 + i) * R + r0 + threadIdx.x;
        oh[o] = h; ol[o] = l;
    }
}

// ------------------------- HMMA GEMM: C[4096x512] = A @ W^T + bias -------------------------
// block: 128 threads (4 warps), tile 64(m) x 64(n), k-chunks of 64.
#define GS 72   // smem row stride in bf16
__global__ __launch_bounds__(128) void hgemm(
    const bf16* __restrict__ Ah, const bf16* __restrict__ Al,
    const bf16* __restrict__ Bh, const bf16* __restrict__ Bl,
    const float* __restrict__ bias, float* __restrict__ out, int mode) {
    __shared__ bf16 XH[64 * GS], XL[64 * GS], WH[64 * GS], WL[64 * GS];
    const int tid = threadIdx.x, w = tid >> 5, lane = tid & 31;
    const int m0 = blockIdx.y * 64, n0 = blockIdx.x * 64;
    const uint32_t sXH = smem_u32(XH), sXL = smem_u32(XL);
    const uint32_t sWH = smem_u32(WH), sWL = smem_u32(WL);

    float c[8][4];
#pragma unroll
    for (int i = 0; i < 8; i++) { c[i][0]=c[i][1]=c[i][2]=c[i][3]=0.f; }

    const int arow = w * 16 + (lane & 15), acolo = (lane >> 4) * 8;
    const int brow = lane & 7, bg = (lane >> 3) * 8;

    for (int kc = 0; kc < 8; kc++) {
        for (int u = tid; u < 512; u += 128) {
            int r = u >> 3, cc = u & 7;
            *reinterpret_cast<uint4*>(&XH[r * GS + cc * 8]) =
                *reinterpret_cast<const uint4*>(Ah + (size_t)(m0 + r) * D_ + kc * 64 + cc * 8);
            *reinterpret_cast<uint4*>(&XL[r * GS + cc * 8]) =
                *reinterpret_cast<const uint4*>(Al + (size_t)(m0 + r) * D_ + kc * 64 + cc * 8);
            *reinterpret_cast<uint4*>(&WH[r * GS + cc * 8]) =
                *reinterpret_cast<const uint4*>(Bh + (size_t)(n0 + r) * D_ + kc * 64 + cc * 8);
            *reinterpret_cast<uint4*>(&WL[r * GS + cc * 8]) =
                *reinterpret_cast<const uint4*>(Bl + (size_t)(n0 + r) * D_ + kc * 64 + cc * 8);
        }
        __syncthreads();
        uint32_t ah[4][4], al[4][4];
#pragma unroll
        for (int kt = 0; kt < 4; kt++) {
            uint32_t off = (uint32_t)(arow * GS + kt * 16 + acolo) * 2;
            ldsm4(sXH + off, ah[kt][0], ah[kt][1], ah[kt][2], ah[kt][3]);
            ldsm4(sXL + off, al[kt][0], al[kt][1], al[kt][2], al[kt][3]);
        }
#pragma unroll
        for (int nt = 0; nt < 8; nt++) {
            uint32_t bh[8], bl[8];
            uint32_t o0 = (uint32_t)((nt * 8 + brow) * GS + bg) * 2;
            uint32_t o1 = (uint32_t)((nt * 8 + brow) * GS + 32 + bg) * 2;
            ldsm4(sWH + o0, bh[0], bh[1], bh[2], bh[3]);
            ldsm4(sWH + o1, bh[4], bh[5], bh[6], bh[7]);
            ldsm4(sWL + o0, bl[0], bl[1], bl[2], bl[3]);
            ldsm4(sWL + o1, bl[4], bl[5], bl[6], bl[7]);
#pragma unroll
            for (int kt = 0; kt < 4; kt++) {
                mma_bf(c[nt], ah[kt], bh[2*kt], bh[2*kt+1]);
                mma_bf(c[nt], ah[kt], bl[2*kt], bl[2*kt+1]);
                mma_bf(c[nt], al[kt], bh[2*kt], bh[2*kt+1]);
            }
        }
        __syncthreads();
    }

    int row = m0 + w * 16 + (lane >> 2);
#pragma unroll
    for (int nt = 0; nt < 8; nt++) {
        int n = n0 + nt * 8 + (lane & 3) * 2;
        float b0 = bias[n], b1 = bias[n + 1];
        float2 v0 = make_float2(c[nt][0] + b0, c[nt][1] + b1);
        float2 v1 = make_float2(c[nt][2] + b0, c[nt][3] + b1);
        if (mode == 0) {
            *reinterpret_cast<float2*>(out + (size_t)row * D_ + n) = v0;
            *reinterpret_cast<float2*>(out + (size_t)(row + 8) * D_ + n) = v1;
        } else {
            int h = n >> 6, col = n & 63;
            *reinterpret_cast<float2*>(out + ((size_t)h * S_ + row) * PD_ + col) = v0;
            *reinterpret_cast<float2*>(out + ((size_t)h * S_ + row + 8) * PD_ + col) = v1;
        }
    }
}

// ------------------------- fused attention (HMMA) -------------------------
// block: 256 threads (8 warps), q-tile 128, k-tiles of 64.
#define A_QH 0
#define A_QL (128 * GS * 2)
#define A_KH (A_QL + 128 * GS * 2)
#define A_KL (A_KH + 64 * GS * 2)
#define A_VH (A_KL + 64 * GS * 2)
#define A_VL (A_VH + 64 * GS * 2)
#define A_SMEM (A_VL + 64 * GS * 2)

__global__ __launch_bounds__(256) void attn_hmma(float* __restrict__ wts) {
    extern __shared__ char sm[];
    const uint32_t sb = smem_u32(sm);
    const int tid = threadIdx.x, w = tid >> 5, lane = tid & 31;
    const int h = blockIdx.y, q0 = blockIdx.x * 128;

    // stage Q (128 x 64 hi/lo)
    {
        const bf16* qhp = g_qh + ((size_t)h * S_ + q0) * PD_;
        const bf16* qlp = g_ql + ((size_t)h * S_ + q0) * PD_;
        for (int u = tid; u < 1024; u += 256) {
            int r = u >> 3, cc = u & 7;
            *reinterpret_cast<uint4*>(sm + A_QH + (r * GS + cc * 8) * 2) =
                *reinterpret_cast<const uint4*>(qhp + (size_t)r * PD_ + cc * 8);
            *reinterpret_cast<uint4*>(sm + A_QL + (r * GS + cc * 8) * 2) =
                *reinterpret_cast<const uint4*>(qlp + (size_t)r * PD_ + cc * 8);
        }
    }
    __syncthreads();

    const int arow = w * 16 + (lane & 15), acolo = (lane >> 4) * 8;
    const int brow = lane & 7, bg = (lane >> 3) * 8;

    uint32_t qh[4][4], ql[4][4];
#pragma unroll
    for (int kt = 0; kt < 4; kt++) {
        uint32_t off = (uint32_t)(arow * GS + kt * 16 + acolo) * 2;
        ldsm4(sb + A_QH + off, qh[kt][0], qh[kt][1], qh[kt][2], qh[kt][3]);
        ldsm4(sb + A_QL + off, ql[kt][0], ql[kt][1], ql[kt][2], ql[kt][3]);
    }

    float o[8][4];
#pragma unroll
    for (int i = 0; i < 8; i++) { o[i][0]=o[i][1]=o[i][2]=o[i][3]=0.f; }
    float m0 = -CUDART_INF_F, m1 = -CUDART_INF_F, l0 = 0.f, l1 = 0.f;

    const bf16* khb = g_kh + (size_t)h * S_ * PD_;
    const bf16* klb = g_kl + (size_t)h * S_ * PD_;
    const bf16* vhb = g_vth + (size_t)h * PD_ * S_;
    const bf16* vlb = g_vtl + (size_t)h * PD_ * S_;

    for (int kt64 = 0; kt64 < 64; kt64++) {
        // load K tile (64 keys x 64 pd) and V^T tile (64 d x 64 keys)
        for (int u = tid; u < 512; u += 256) {
            int r = u >> 3, cc = u & 7;
            *reinterpret_cast<uint4*>(sm + A_KH + (r * GS + cc * 8) * 2) =
                *reinterpret_cast<const uint4*>(khb + ((size_t)kt64 * 64 + r) * PD_ + cc * 8);
            *reinterpret_cast<uint4*>(sm + A_KL + (r * GS + cc * 8) * 2) =
                *reinterpret_cast<const uint4*>(klb + ((size_t)kt64 * 64 + r) * PD_ + cc * 8);
            *reinterpret_cast<uint4*>(sm + A_VH + (r * GS + cc * 8) * 2) =
                *reinterpret_cast<const uint4*>(vhb + (size_t)r * S_ + kt64 * 64 + cc * 8);
            *reinterpret_cast<uint4*>(sm + A_VL + (r * GS + cc * 8) * 2) =
                *reinterpret_cast<const uint4*>(vlb + (size_t)r * S_ + kt64 * 64 + cc * 8);
        }
        __syncthreads();

        // ---- S = Q K^T (scaled) ----
        float s[8][4];
#pragma unroll
        for (int nt = 0; nt < 8; nt++) {
            uint32_t bh[8], bl[8];
            uint32_t o0 = (uint32_t)((nt * 8 + brow) * GS + bg) * 2;
            uint32_t o1 = (uint32_t)((nt * 8 + brow) * GS + 32 + bg) * 2;
            ldsm4(sb + A_KH + o0, bh[0], bh[1], bh[2], bh[3]);
            ldsm4(sb + A_KH + o1, bh[4], bh[5], bh[6], bh[7]);
            ldsm4(sb + A_KL + o0, bl[0], bl[1], bl[2], bl[3]);
            ldsm4(sb + A_KL + o1, bl[4], bl[5], bl[6], bl[7]);
            float cc[4] = {0.f, 0.f, 0.f, 0.f};
#pragma unroll
            for (int kt = 0; kt < 4; kt++) {
                mma_bf(cc, qh[kt], bh[2*kt], bh[2*kt+1]);
                mma_bf(cc, qh[kt], bl[2*kt], bl[2*kt+1]);
                mma_bf(cc, ql[kt], bh[2*kt], bh[2*kt+1]);
            }
            s[nt][0] = cc[0] * 0.125f; s[nt][1] = cc[1] * 0.125f;
            s[nt][2] = cc[2] * 0.125f; s[nt][3] = cc[3] * 0.125f;
        }

        // ---- write raw scores ----
        {
            size_t row = (size_t)h * S_ + q0 + w * 16 + (lane >> 2);
            float* wp0 = wts + row * S_ + kt64 * 64 + (lane & 3) * 2;
            float* wp1 = wp0 + 8 * (size_t)S_;
#pragma unroll
            for (int nt = 0; nt < 8; nt++) {
                *reinterpret_cast<float2*>(wp0 + nt * 8) = make_float2(s[nt][0], s[nt][1]);
                *reinterpret_cast<float2*>(wp1 + nt * 8) = make_float2(s[nt][2], s[nt][3]);
            }
        }

        // ---- online softmax ----
        float mx0 = -CUDART_INF_F, mx1 = -CUDART_INF_F;
#pragma unroll
        for (int nt = 0; nt < 8; nt++) {
            mx0 = fmaxf(mx0, fmaxf(s[nt][0], s[nt][1]));
            mx1 = fmaxf(mx1, fmaxf(s[nt][2], s[nt][3]));
        }
        mx0 = fmaxf(mx0, __shfl_xor_sync(0xffffffffu, mx0, 1));
        mx0 = fmaxf(mx0, __shfl_xor_sync(0xffffffffu, mx0, 2));
        mx1 = fmaxf(mx1, __shfl_xor_sync(0xffffffffu, mx1, 1));
        mx1 = fmaxf(mx1, __shfl_xor_sync(0xffffffffu, mx1, 2));
        float mn0 = fmaxf(m0, mx0), mn1 = fmaxf(m1, mx1);
        float cr0 = __expf(m0 - mn0), cr1 = __expf(m1 - mn1);
#pragma unroll
        for (int nt = 0; nt < 8; nt++) {
            o[nt][0] *= cr0; o[nt][1] *= cr0; o[nt][2] *= cr1; o[nt][3] *= cr1;
        }
        float ps0 = 0.f, ps1 = 0.f;
#pragma unroll
        for (int nt = 0; nt < 8; nt++) {
            s[nt][0] = __expf(s[nt][0] - mn0); s[nt][1] = __expf(s[nt][1] - mn0);
            s[nt][2] = __expf(s[nt][2] - mn1); s[nt][3] = __expf(s[nt][3] - mn1);
            ps0 += s[nt][0] + s[nt][1];
            ps1 += s[nt][2] + s[nt][3];
        }
        ps0 += __shfl_xor_sync(0xffffffffu, ps0, 1);
        ps0 += __shfl_xor_sync(0xffffffffu, ps0, 2);
        ps1 += __shfl_xor_sync(0xffffffffu, ps1, 1);
        ps1 += __shfl_xor_sync(0xffffffffu, ps1, 2);
        l0 = l0 * cr0 + ps0; l1 = l1 * cr1 + ps1;
        m0 = mn0; m1 = mn1;

        // ---- repack P (C-frag -> A-frag), split hi/lo ----
        uint32_t pah[4][4], pal[4][4];
#pragma unroll
        for (int jj = 0; jj < 4; jj++) {
            bsplitpack(s[2*jj][0],   s[2*jj][1],   pah[jj][0], pal[jj][0]);
            bsplitpack(s[2*jj][2],   s[2*jj][3],   pah[jj][1], pal[jj][1]);
            bsplitpack(s[2*jj+1][0], s[2*jj+1][1], pah[jj][2], pal[jj][2]);
            bsplitpack(s[2*jj+1][2], s[2*jj+1][3], pah[jj][3], pal[jj][3]);
        }

        // ---- O += P @ V ----
#pragma unroll
        for (int dt = 0; dt < 8; dt++) {
            uint32_t vh[8], vl[8];
            uint32_t o0 = (uint32_t)((dt * 8 + brow) * GS + bg) * 2;
            uint32_t o1 = (uint32_t)((dt * 8 + brow) * GS + 32 + bg) * 2;
            ldsm4(sb + A_VH + o0, vh[0], vh[1], vh[2], vh[3]);
            ldsm4(sb + A_VH + o1, vh[4], vh[5], vh[6], vh[7]);
            ldsm4(sb + A_VL + o0, vl[0], vl[1], vl[2], vl[3]);
            ldsm4(sb + A_VL + o1, vl[4], vl[5], vl[6], vl[7]);
#pragma unroll
            for (int jj = 0; jj < 4; jj++) {
                mma_bf(o[dt], pah[jj], vh[2*jj], vh[2*jj+1]);
                mma_bf(o[dt], pah[jj], vl[2*jj], vl[2*jj+1]);
                mma_bf(o[dt], pal[jj], vh[2*jj], vh[2*jj+1]);
            }
        }
        __syncthreads();
    }

    // ---- epilogue ----
    int row = q0 + w * 16 + (lane >> 2);
    float inv0 = 1.0f / l0, inv1 = 1.0f / l1;
    if ((lane & 3) == 0) {
        g_m[h * S_ + row] = m0;       g_linv[h * S_ + row] = inv0;
        g_m[h * S_ + row + 8] = m1;   g_linv[h * S_ + row + 8] = inv1;
    }
#pragma unroll
    for (int dt = 0; dt < 8; dt++) {
        int col = h * PD_ + dt * 8 + (lane & 3) * 2;
        *reinterpret_cast<float2*>(g_attn + (size_t)row * D_ + col) =
            make_float2(o[dt][0] * inv0, o[dt][1] * inv0);
        *reinterpret_cast<float2*>(g_attn + (size_t)(row + 8) * D_ + col) =
            make_float2(o[dt][2] * inv1, o[dt][3] * inv1);
    }
}

// ------------------------- normalize weights in place -------------------------
__global__ __launch_bounds__(256) void norm_weights(float* __restrict__ w) {
    size_t idx = (((size_t)blockIdx.x * 256) + threadIdx.x) << 2;
    size_t row = idx >> 12;
    float m = g_m[row], inv = g_linv[row];
    float4 v = *reinterpret_cast<float4*>(w + idx);
    v.x = __expf(v.x - m) * inv;
    v.y = __expf(v.y - m) * inv;
    v.z = __expf(v.z - m) * inv;
    v.w = __expf(v.w - m) * inv;
    *reinterpret_cast<float4*>(w + idx) = v;
}

// ---------------------------------------------------------------------------
extern "C" void kernel_launch(void* const* d_in, const int* in_sizes, int n_in,
                              void* d_out, int out_size) {
    const float* x1 = (const float*)d_in[0];
    const float* x2 = (const float*)d_in[1];
    const float* x3 = (const float*)d_in[2];
    const float* Wq = (const float*)d_in[3];
    const float* bq = (const float*)d_in[4];
    const float* Wk = (const float*)d_in[5];
    const float* bk = (const float*)d_in[6];
    const float* Wv = (const float*)d_in[7];
    const float* bv = (const float*)d_in[8];
    const float* Wo = (const float*)d_in[9];
    const float* bo = (const float*)d_in[10];
    float* out = (float*)d_out;
    float* wts = out + (size_t)S_ * D_;

    cudaFuncSetAttribute(attn_hmma, cudaFuncAttributeMaxDynamicSharedMemorySize, A_SMEM);

    bf16 *xh, *xl, *wth, *wtl, *qh, *ql, *kh, *kl, *vth, *vtl, *ah, *al;
    float *qb, *kb, *vb, *ab;
    cudaGetSymbolAddress((void**)&xh, g_xh);
    cudaGetSymbolAddress((void**)&xl, g_xl);
    cudaGetSymbolAddress((void**)&wth, g_wth);
    cudaGetSymbolAddress((void**)&wtl, g_wtl);
    cudaGetSymbolAddress((void**)&qb, g_q);
    cudaGetSymbolAddress((void**)&kb, g_k);
    cudaGetSymbolAddress((void**)&vb, g_v);
    cudaGetSymbolAddress((void**)&qh, g_qh);
    cudaGetSymbolAddress((void**)&ql, g_ql);
    cudaGetSymbolAddress((void**)&kh, g_kh);
    cudaGetSymbolAddress((void**)&kl, g_kl);
    cudaGetSymbolAddress((void**)&vth, g_vth);
    cudaGetSymbolAddress((void**)&vtl, g_vtl);
    cudaGetSymbolAddress((void**)&ab, g_attn);
    cudaGetSymbolAddress((void**)&ah, g_ah);
    cudaGetSymbolAddress((void**)&al, g_al);

    const size_t NX = (size_t)S_ * D_;
    const size_t NW = (size_t)D_ * D_;
    const int SPB = (int)(NX / 1024);
    dim3 tb(32, 8);

    split_kernel<<<SPB, 256>>>(x1, xh + 0*NX, xl + 0*NX);
    split_kernel<<<SPB, 256>>>(x2, xh + 1*NX, xl + 1*NX);
    split_kernel<<<SPB, 256>>>(x3, xh + 2*NX, xl + 2*NX);
    transpose_split<<<dim3(16,16,1), tb>>>(Wq, wth + 0*NW, wtl + 0*NW, D_, D_);
    transpose_split<<<dim3(16,16,1), tb>>>(Wk, wth + 1*NW, wtl + 1*NW, D_, D_);
    transpose_split<<<dim3(16,16,1), tb>>>(Wv, wth + 2*NW, wtl + 2*NW, D_, D_);
    transpose_split<<<dim3(16,16,1), tb>>>(Wo, wth + 3*NW, wtl + 3*NW, D_, D_);

    dim3 gg(D_/64, S_/64);
    hgemm<<<gg, 128>>>(xh + 0*NX, xl + 0*NX, wth + 0*NW, wtl + 0*NW, bq, qb, 1);
    hgemm<<<gg, 128>>>(xh + 1*NX, xl + 1*NX, wth + 1*NW, wtl + 1*NW, bk, kb, 1);
    hgemm<<<gg, 128>>>(xh + 2*NX, xl + 2*NX, wth + 2*NW, wtl + 2*NW, bv, vb, 1);

    split_kernel<<<SPB, 256>>>(qb, qh, ql);
    split_kernel<<<SPB, 256>>>(kb, kh, kl);
    transpose_split<<<dim3(PD_/32, S_/32, H_), tb>>>(vb, vth, vtl, S_, PD_);

    attn_hmma<<<dim3(S_/128, H_), 256, A_SMEM>>>(wts);

    norm_weights<<<(int)((H_ * (size_t)S_ * S_) / (4 * 256)), 256>>>(wts);

    split_kernel<<<SPB, 256>>>(ab, ah, al);
    hgemm<<<gg, 128>>>(ah, al, wth + 3*NW, wtl + 3*NW, bo, out, 0);
}